// round 14
// baseline (speedup 1.0000x reference)
#include <cuda_runtime.h>
#include <cuda_bf16.h>
#include <cstdint>

#define BB 8
#define TT 2048
#define DD 1024
#define MT (BB * TT)   // 16384 rows

#define TILE_PK 10240               // one packed tile: 128 rows x 80 B
#define XBLK 128                    // x row-blocks (MT/128)
#define WBLK 24                     // stacked W row-blocks (3072/128)
#define NCHK 32                     // K chunks of 32

// ---------------- scratch (__device__ globals; no allocs allowed) -----------
__device__ float g_q[(size_t)MT * DD];
__device__ float g_k[(size_t)MT * DD];
__device__ float g_v[(size_t)MT * DD];
__device__ uint8_t g_xpack_hi[(size_t)XBLK * NCHK * TILE_PK];   // 40 MB
__device__ uint8_t g_xpack_lo[(size_t)XBLK * NCHK * TILE_PK];
__device__ uint8_t g_wpack_hi[(size_t)WBLK * NCHK * TILE_PK];   // 7.5 MB
__device__ uint8_t g_wpack_lo[(size_t)WBLK * NCHK * TILE_PK];
// single-pass scan state
#define NCH 16
#define LCH 128
__device__ float g_incl[NCH * BB * DD];
__device__ int   g_flag[NCH * BB * DD];

// ---------------- helpers ----------------------------------------------------
__device__ __forceinline__ uint32_t smem_to_u32(const void* p) {
    uint32_t a;
    asm("{ .reg .u64 t; cvta.to.shared.u64 t, %1; cvt.u32.u64 %0, t; }"
        : "=r"(a) : "l"(p));
    return a;
}
__device__ __forceinline__ void cp_bulk(uint32_t sdst, const void* gsrc,
                                        uint32_t bytes, uint32_t mbar) {
    asm volatile("cp.async.bulk.shared::cta.global.mbarrier::complete_tx::bytes "
                 "[%0], [%1], %2, [%3];"
                 :: "r"(sdst), "l"(gsrc), "r"(bytes), "r"(mbar) : "memory");
}
#define MBARRIER_INIT(mbar, count) \
    asm volatile("mbarrier.init.shared.b64 [%0], %1;" \
                 :: "r"((uint32_t)(mbar)), "r"((uint32_t)(count)) : "memory")
#define MBARRIER_EXPECT_TX(mbar, bytes) \
    asm volatile("mbarrier.arrive.expect_tx.shared.b64 _, [%0], %1;" \
                 :: "r"((uint32_t)(mbar)), "r"((uint32_t)(bytes)) : "memory")
#define MBARRIER_WAIT_PARITY(mbar_smem_addr, phase_parity) do { \
    uint32_t _mbar = (uint32_t)(mbar_smem_addr); \
    uint32_t _parity = (uint32_t)(phase_parity); \
    uint32_t _done; \
    asm volatile("{\n\t.reg .pred p;\n\t" \
        "mbarrier.try_wait.parity.acquire.cta.shared::cta.b64 p, [%1], %2;\n\t" \
        "selp.b32 %0, 1, 0, p;\n\t}" : "=r"(_done) : "r"(_mbar), "r"(_parity) : "memory"); \
    if (!_done) { \
        asm volatile("{\n\t.reg .pred P1;\n\t" \
            "WAIT_LOOP_%=:\n\t" \
            "mbarrier.try_wait.parity.acquire.cta.shared::cta.b64 P1, [%0], %1, 0x989680;\n\t" \
            "@P1 bra.uni WAIT_DONE_%=;\n\t" \
            "bra.uni WAIT_LOOP_%=;\n\t" \
            "WAIT_DONE_%=:\n\t}" :: "r"(_mbar), "r"(_parity) : "memory"); \
    } \
} while (0)
__device__ __forceinline__ void ldm_x4(uint32_t* r, uint32_t addr) {
    asm volatile("ldmatrix.sync.aligned.m8n8.x4.shared.b16 {%0,%1,%2,%3}, [%4];"
                 : "=r"(r[0]), "=r"(r[1]), "=r"(r[2]), "=r"(r[3]) : "r"(addr));
}
__device__ __forceinline__ void mma_bf16(float* c, const uint32_t* a, const uint32_t* b) {
    asm volatile("mma.sync.aligned.m16n8k16.row.col.f32.bf16.bf16.f32 "
                 "{%0,%1,%2,%3}, {%4,%5,%6,%7}, {%8,%9}, {%0,%1,%2,%3};"
                 : "+f"(c[0]), "+f"(c[1]), "+f"(c[2]), "+f"(c[3])
                 : "r"(a[0]), "r"(a[1]), "r"(a[2]), "r"(a[3]),
                   "r"(b[0]), "r"(b[1]));
}

// ---------------- split fp32 -> bf16 hi/lo, packed tile layout ---------------
__global__ __launch_bounds__(256) void split_pack_kernel(const float* __restrict__ src,
                                                         uint8_t* __restrict__ hi,
                                                         uint8_t* __restrict__ lo,
                                                         int n4) {
    int i = blockIdx.x * blockDim.x + threadIdx.x;
    if (i >= n4) return;
    int r = i >> 8;               // global row (256 float4 per row)
    int c = (i & 255) << 2;       // starting col
    float4 v = ((const float4*)src)[i];
    __nv_bfloat16 h[4], l[4];
    float f[4] = {v.x, v.y, v.z, v.w};
#pragma unroll
    for (int j = 0; j < 4; j++) {
        h[j] = __float2bfloat16_rn(f[j]);
        l[j] = __float2bfloat16_rn(f[j] - __bfloat162float(h[j]));
    }
    size_t off = (size_t)((r >> 7) * NCHK + (c >> 5)) * TILE_PK
               + (size_t)(r & 127) * 80 + (size_t)((c & 31) << 1);
    *(uint2*)(hi + off) = *(uint2*)h;
    *(uint2*)(lo + off) = *(uint2*)l;
}

// ---------------- fused QKV HMMA bf16 split GEMM, bulk-async loads -----------
#define ROWB 80
#define ST_A_HI 0
#define ST_A_LO (128 * ROWB)               // 10240
#define ST_B_HI (2 * 128 * ROWB)           // 20480 (2 tiles)
#define ST_B_LO (ST_B_HI + 256 * ROWB)     // 40960 (2 tiles)
#define STAGE_B (ST_B_LO + 256 * ROWB)     // 61440
#define NSTAGE 3
#define SM_MBAR (NSTAGE * STAGE_B)         // mbarriers after stages

__global__ __launch_bounds__(256, 1) void gemm_qkv_kernel(
    const float* __restrict__ bq, const float* __restrict__ bk,
    const float* __restrict__ bv,
    float* __restrict__ Cq, float* __restrict__ Ck, float* __restrict__ Cv) {
    extern __shared__ char smem[];
    const uint32_t smem_base = smem_to_u32(smem);
    const int tid = threadIdx.x;
    const int wid = tid >> 5;
    const int lane = tid & 31;
    const int warp_m = wid & 1;          // 2 warps in M (64 rows each)
    const int warp_n = wid >> 1;         // 4 warps in N (64 cols each)
    const int bm = blockIdx.y * 128;
    const int bn = blockIdx.x * 256;     // 0..3071 within stacked W
    const int seg = bn >> 10;            // 0=q, 1=k, 2=v
    const int cn = bn & (DD - 1);

    const float* bias = (seg == 0) ? bq : (seg == 1) ? bk : bv;
    float* C = (seg == 0) ? Cq : (seg == 1) ? Ck : Cv;

    const uint8_t* axh = g_xpack_hi + (size_t)blockIdx.y * NCHK * TILE_PK;
    const uint8_t* axl = g_xpack_lo + (size_t)blockIdx.y * NCHK * TILE_PK;
    const uint8_t* bwh = g_wpack_hi + (size_t)(blockIdx.x * 2) * NCHK * TILE_PK;
    const uint8_t* bwl = g_wpack_lo + (size_t)(blockIdx.x * 2) * NCHK * TILE_PK;

    const int lr = lane & 7;
    const int g = lane >> 3;                       // 0..3
    const uint32_t a_row = warp_m * 64 + (g & 1) * 8 + lr;   // + mt*16
    const uint32_t a_koff = (g >> 1) * 8;
    const uint32_t b_row = warp_n * 64 + ((lane >> 4) << 3) + lr;  // + j*16
    const uint32_t b_koff = ((lane >> 3) & 1) * 8;

    float acc[4][8][4];
#pragma unroll
    for (int i = 0; i < 4; i++)
#pragma unroll
        for (int j = 0; j < 8; j++)
#pragma unroll
            for (int r = 0; r < 4; r++) acc[i][j][r] = 0.f;

    if (tid == 0) {
#pragma unroll
        for (int s = 0; s < NSTAGE; s++)
            MBARRIER_INIT(smem_base + SM_MBAR + s * 8, 1);
    }
    __syncthreads();

    auto issue = [&](int ch) {
        const int s = ch % NSTAGE;
        const uint32_t mbar = smem_base + SM_MBAR + s * 8;
        const uint32_t sb = smem_base + s * STAGE_B;
        MBARRIER_EXPECT_TX(mbar, STAGE_B);
        cp_bulk(sb + ST_A_HI,           axh + (size_t)ch * TILE_PK, TILE_PK, mbar);
        cp_bulk(sb + ST_A_LO,           axl + (size_t)ch * TILE_PK, TILE_PK, mbar);
        cp_bulk(sb + ST_B_HI,           bwh + (size_t)ch * TILE_PK, TILE_PK, mbar);
        cp_bulk(sb + ST_B_HI + TILE_PK, bwh + (size_t)(NCHK + ch) * TILE_PK, TILE_PK, mbar);
        cp_bulk(sb + ST_B_LO,           bwl + (size_t)ch * TILE_PK, TILE_PK, mbar);
        cp_bulk(sb + ST_B_LO + TILE_PK, bwl + (size_t)(NCHK + ch) * TILE_PK, TILE_PK, mbar);
    };

    if (tid == 0) { issue(0); issue(1); }

    int s = 0, p = 0;
    for (int ch = 0; ch < NCHK; ch++) {
        MBARRIER_WAIT_PARITY(smem_base + SM_MBAR + s * 8, p);
        __syncthreads();
        if (tid == 0 && ch + 2 < NCHK) issue(ch + 2);

        const uint32_t base = smem_base + s * STAGE_B;
#pragma unroll
        for (int ks = 0; ks < 2; ks++) {
            uint32_t ahi[4][4], alo[4][4], bhi[4][4], blo[4][4];
#pragma unroll
            for (int mt = 0; mt < 4; mt++) {
                uint32_t ar = base + (a_row + mt * 16) * ROWB
                            + (ks * 16 + a_koff) * 2;
                ldm_x4(ahi[mt], ar + ST_A_HI);
                ldm_x4(alo[mt], ar + ST_A_LO);
            }
#pragma unroll
            for (int j = 0; j < 4; j++) {
                uint32_t br = base + (b_row + j * 16) * ROWB
                            + (ks * 16 + b_koff) * 2;
                ldm_x4(bhi[j], br + ST_B_HI);
                ldm_x4(blo[j], br + ST_B_LO);
            }
#pragma unroll
            for (int mt = 0; mt < 4; mt++)
#pragma unroll
                for (int nt = 0; nt < 8; nt++)
                    mma_bf16(acc[mt][nt], ahi[mt], &bhi[nt >> 1][(nt & 1) * 2]);
#pragma unroll
            for (int mt = 0; mt < 4; mt++)
#pragma unroll
                for (int nt = 0; nt < 8; nt++)
                    mma_bf16(acc[mt][nt], ahi[mt], &blo[nt >> 1][(nt & 1) * 2]);
#pragma unroll
            for (int mt = 0; mt < 4; mt++)
#pragma unroll
                for (int nt = 0; nt < 8; nt++)
                    mma_bf16(acc[mt][nt], alo[mt], &bhi[nt >> 1][(nt & 1) * 2]);
        }
        s++;
        if (s == NSTAGE) { s = 0; p ^= 1; }
    }

    const int qr = lane >> 2;           // 0..7
    const int qc = (lane & 3) * 2;      // 0,2,4,6
#pragma unroll
    for (int mt = 0; mt < 4; mt++) {
#pragma unroll
        for (int nt = 0; nt < 8; nt++) {
            const int row0 = bm + warp_m * 64 + mt * 16 + qr;
            const int col = cn + warp_n * 64 + nt * 8 + qc;
            const float2 bvv = *(const float2*)&bias[col];
            float2 v0, v1;
            v0.x = acc[mt][nt][0] + bvv.x;
            v0.y = acc[mt][nt][1] + bvv.y;
            v1.x = acc[mt][nt][2] + bvv.x;
            v1.y = acc[mt][nt][3] + bvv.y;
            *(float2*)&C[(size_t)row0 * DD + col] = v0;
            *(float2*)&C[(size_t)(row0 + 8) * DD + col] = v1;
        }
    }
}

// ---------------- single-pass scan with decoupled lookback -------------------
// One thread per (b, d, chunk). Local scan cached in smem (t-major), inclusive
// chunk-final published with release; successor spins with acquire.
__global__ __launch_bounds__(256) void scan_onepass_kernel(
    const float* __restrict__ decay, float* __restrict__ out) {
    extern __shared__ float smem_mem[];    // [LCH][256]
    const int tid = threadIdx.x;
    const int x = blockIdx.x * 256 + tid;  // item index
    const int d = x & (DD - 1);
    const int b = (x >> 10) & (BB - 1);
    const int c = x >> 13;                 // chunk (constant per CTA)

    const float dec = decay[d];
    const size_t base = (size_t)b * TT * DD + (size_t)c * LCH * DD + d;

    // pass A: local scan, cache mem_t in smem
    float mem = 0.f;
#pragma unroll 4
    for (int t = 0; t < LCH; t++) {
        size_t off = base + (size_t)t * DD;
        mem = fmaf(dec, mem, g_k[off] * g_v[off]);
        smem_mem[t * 256 + tid] = mem;
    }

    // dec^LCH
    float pL = dec;
#pragma unroll
    for (int i = 0; i < 7; i++) pL *= pL;

    // lookback: get inclusive final of predecessor chunk (same b,d)
    float carry = 0.f;
    if (c > 0) {
        const int pred = x - BB * DD;      // (c-1, b, d)
        const int* fp = g_flag + pred;
        int f;
        do {
            asm volatile("ld.global.acquire.gpu.b32 %0, [%1];" : "=r"(f) : "l"(fp));
        } while (f == 0);
        asm volatile("ld.global.cg.f32 %0, [%1];" : "=f"(carry) : "l"(g_incl + pred));
    }

    // publish my inclusive final
    {
        float incl = fmaf(pL, carry, mem);
        asm volatile("st.global.cg.f32 [%0], %1;" :: "l"(g_incl + x), "f"(incl));
        asm volatile("st.global.release.gpu.b32 [%0], %1;" :: "l"(g_flag + x), "r"(1));
    }

    // pass B: apply carry, multiply by q, write out
    float factor = dec;
#pragma unroll 4
    for (int t = 0; t < LCH; t++) {
        size_t off = base + (size_t)t * DD;
        float m = fmaf(factor, carry, smem_mem[t * 256 + tid]);
        out[off] = g_q[off] * m;
        factor *= dec;
    }
}

// ---------------- launch -----------------------------------------------------
extern "C" void kernel_launch(void* const* d_in, const int* in_sizes, int n_in,
                              void* d_out, int out_size) {
    const float* x     = (const float*)d_in[0];
    const float* Wq    = (const float*)d_in[1];
    const float* bq    = (const float*)d_in[2];
    const float* Wk    = (const float*)d_in[3];
    const float* bk    = (const float*)d_in[4];
    const float* Wv    = (const float*)d_in[5];
    const float* bv    = (const float*)d_in[6];
    const float* decay = (const float*)d_in[7];
    float* out = (float*)d_out;

    float *q_p, *k_p, *v_p;
    uint8_t *xh_p, *xl_p, *wh_p, *wl_p;
    int* flag_p;
    cudaGetSymbolAddress((void**)&q_p, g_q);
    cudaGetSymbolAddress((void**)&k_p, g_k);
    cudaGetSymbolAddress((void**)&v_p, g_v);
    cudaGetSymbolAddress((void**)&xh_p, g_xpack_hi);
    cudaGetSymbolAddress((void**)&xl_p, g_xpack_lo);
    cudaGetSymbolAddress((void**)&wh_p, g_wpack_hi);
    cudaGetSymbolAddress((void**)&wl_p, g_wpack_lo);
    cudaGetSymbolAddress((void**)&flag_p, g_flag);

    const int XN4 = MT * DD / 4;                 // 4M
    const int WN4 = DD * DD / 4;                 // 256K
    const size_t WSEG = (size_t)8 * NCHK * TILE_PK;

    // reset lookback flags (replay-safe)
    cudaMemsetAsync(flag_p, 0, (size_t)NCH * BB * DD * sizeof(int));

    // packed hi/lo splits
    split_pack_kernel<<<XN4 / 256, 256>>>(x, xh_p, xl_p, XN4);
    split_pack_kernel<<<WN4 / 256, 256>>>(Wq, wh_p + 0 * WSEG, wl_p + 0 * WSEG, WN4);
    split_pack_kernel<<<WN4 / 256, 256>>>(Wk, wh_p + 1 * WSEG, wl_p + 1 * WSEG, WN4);
    split_pack_kernel<<<WN4 / 256, 256>>>(Wv, wh_p + 2 * WSEG, wl_p + 2 * WSEG, WN4);

    // fused QKV HMMA GEMM (single launch, N=3072, bulk-async loads)
    const int smem_bytes = NSTAGE * STAGE_B + 64;   // 184384
    cudaFuncSetAttribute(gemm_qkv_kernel, cudaFuncAttributeMaxDynamicSharedMemorySize, smem_bytes);
    dim3 grid(3 * DD / 256, MT / 128);              // (12, 128) = 1536 CTAs
    gemm_qkv_kernel<<<grid, 256, smem_bytes>>>(bq, bk, bv, q_p, k_p, v_p);

    // single-pass scan
    const int scan_smem = LCH * 256 * sizeof(float);   // 131072
    cudaFuncSetAttribute(scan_onepass_kernel, cudaFuncAttributeMaxDynamicSharedMemorySize, scan_smem);
    scan_onepass_kernel<<<(NCH * BB * DD) / 256, 256, scan_smem>>>(decay, out);
}

// round 15
// speedup vs baseline: 1.3294x; 1.3294x over previous
#include <cuda_runtime.h>
#include <cuda_bf16.h>
#include <cstdint>

#define BB 8
#define TT 2048
#define DD 1024
#define MT (BB * TT)   // 16384 rows

#define TILE_PK 10240               // one packed tile: 128 rows x 80 B
#define XBLK 128                    // x row-blocks (MT/128)
#define WBLK 24                     // stacked W row-blocks (3072/128)
#define NCHK 32                     // K chunks of 32

// ---------------- scratch (__device__ globals; no allocs allowed) -----------
__device__ float g_q[(size_t)MT * DD];
__device__ float g_k[(size_t)MT * DD];
__device__ float g_v[(size_t)MT * DD];          // holds kv after fused V epilogue
__device__ uint8_t g_xpack_hi[(size_t)XBLK * NCHK * TILE_PK];   // 40 MB
__device__ uint8_t g_xpack_lo[(size_t)XBLK * NCHK * TILE_PK];
__device__ uint8_t g_wpack_hi[(size_t)WBLK * NCHK * TILE_PK];   // 7.5 MB
__device__ uint8_t g_wpack_lo[(size_t)WBLK * NCHK * TILE_PK];
// scan intermediates
#define NCH 16
#define LCH 128
__device__ float g_finals[NCH * BB * DD];
__device__ float g_carries[NCH * BB * DD];

// ---------------- helpers ----------------------------------------------------
__device__ __forceinline__ uint32_t smem_to_u32(const void* p) {
    uint32_t a;
    asm("{ .reg .u64 t; cvta.to.shared.u64 t, %1; cvt.u32.u64 %0, t; }"
        : "=r"(a) : "l"(p));
    return a;
}
__device__ __forceinline__ void cp_bulk(uint32_t sdst, const void* gsrc,
                                        uint32_t bytes, uint32_t mbar) {
    asm volatile("cp.async.bulk.shared::cta.global.mbarrier::complete_tx::bytes "
                 "[%0], [%1], %2, [%3];"
                 :: "r"(sdst), "l"(gsrc), "r"(bytes), "r"(mbar) : "memory");
}
#define MBARRIER_INIT(mbar, count) \
    asm volatile("mbarrier.init.shared.b64 [%0], %1;" \
                 :: "r"((uint32_t)(mbar)), "r"((uint32_t)(count)) : "memory")
#define MBARRIER_EXPECT_TX(mbar, bytes) \
    asm volatile("mbarrier.arrive.expect_tx.shared.b64 _, [%0], %1;" \
                 :: "r"((uint32_t)(mbar)), "r"((uint32_t)(bytes)) : "memory")
#define MBARRIER_WAIT_PARITY(mbar_smem_addr, phase_parity) do { \
    uint32_t _mbar = (uint32_t)(mbar_smem_addr); \
    uint32_t _parity = (uint32_t)(phase_parity); \
    uint32_t _done; \
    asm volatile("{\n\t.reg .pred p;\n\t" \
        "mbarrier.try_wait.parity.acquire.cta.shared::cta.b64 p, [%1], %2;\n\t" \
        "selp.b32 %0, 1, 0, p;\n\t}" : "=r"(_done) : "r"(_mbar), "r"(_parity) : "memory"); \
    if (!_done) { \
        asm volatile("{\n\t.reg .pred P1;\n\t" \
            "WAIT_LOOP_%=:\n\t" \
            "mbarrier.try_wait.parity.acquire.cta.shared::cta.b64 P1, [%0], %1, 0x989680;\n\t" \
            "@P1 bra.uni WAIT_DONE_%=;\n\t" \
            "bra.uni WAIT_LOOP_%=;\n\t" \
            "WAIT_DONE_%=:\n\t}" :: "r"(_mbar), "r"(_parity) : "memory"); \
    } \
} while (0)
__device__ __forceinline__ void ldm_x4(uint32_t* r, uint32_t addr) {
    asm volatile("ldmatrix.sync.aligned.m8n8.x4.shared.b16 {%0,%1,%2,%3}, [%4];"
                 : "=r"(r[0]), "=r"(r[1]), "=r"(r[2]), "=r"(r[3]) : "r"(addr));
}
__device__ __forceinline__ void mma_bf16(float* c, const uint32_t* a, const uint32_t* b) {
    asm volatile("mma.sync.aligned.m16n8k16.row.col.f32.bf16.bf16.f32 "
                 "{%0,%1,%2,%3}, {%4,%5,%6,%7}, {%8,%9}, {%0,%1,%2,%3};"
                 : "+f"(c[0]), "+f"(c[1]), "+f"(c[2]), "+f"(c[3])
                 : "r"(a[0]), "r"(a[1]), "r"(a[2]), "r"(a[3]),
                   "r"(b[0]), "r"(b[1]));
}

// ---------------- split fp32 -> bf16 hi/lo, packed tile layout ---------------
__global__ __launch_bounds__(256) void split_pack_kernel(const float* __restrict__ src,
                                                         uint8_t* __restrict__ hi,
                                                         uint8_t* __restrict__ lo,
                                                         int n4) {
    int i = blockIdx.x * blockDim.x + threadIdx.x;
    if (i >= n4) return;
    int r = i >> 8;               // global row (256 float4 per row)
    int c = (i & 255) << 2;       // starting col
    float4 v = ((const float4*)src)[i];
    __nv_bfloat16 h[4], l[4];
    float f[4] = {v.x, v.y, v.z, v.w};
#pragma unroll
    for (int j = 0; j < 4; j++) {
        h[j] = __float2bfloat16_rn(f[j]);
        l[j] = __float2bfloat16_rn(f[j] - __bfloat162float(h[j]));
    }
    size_t off = (size_t)((r >> 7) * NCHK + (c >> 5)) * TILE_PK
               + (size_t)(r & 127) * 80 + (size_t)((c & 31) << 1);
    *(uint2*)(hi + off) = *(uint2*)h;
    *(uint2*)(lo + off) = *(uint2*)l;
}

// ---------------- fused QKV HMMA bf16 split GEMM, bulk-async loads -----------
// xoff selects the W-column window: bn = (blockIdx.x + xoff) * 256.
// mul != nullptr => epilogue multiplies (acc + bias) elementwise by mul (kv fusion).
#define ROWB 80
#define ST_A_HI 0
#define ST_A_LO (128 * ROWB)               // 10240
#define ST_B_HI (2 * 128 * ROWB)           // 20480 (2 tiles)
#define ST_B_LO (ST_B_HI + 256 * ROWB)     // 40960 (2 tiles)
#define STAGE_B (ST_B_LO + 256 * ROWB)     // 61440
#define NSTAGE 3
#define SM_MBAR (NSTAGE * STAGE_B)         // mbarriers after stages

__global__ __launch_bounds__(256, 1) void gemm_qkv_kernel(
    const float* __restrict__ bq, const float* __restrict__ bk,
    const float* __restrict__ bv,
    float* __restrict__ Cq, float* __restrict__ Ck, float* __restrict__ Cv,
    const float* __restrict__ mul, int xoff) {
    extern __shared__ char smem[];
    const uint32_t smem_base = smem_to_u32(smem);
    const int tid = threadIdx.x;
    const int wid = tid >> 5;
    const int lane = tid & 31;
    const int warp_m = wid & 1;          // 2 warps in M (64 rows each)
    const int warp_n = wid >> 1;         // 4 warps in N (64 cols each)
    const int bx = blockIdx.x + xoff;
    const int bm = blockIdx.y * 128;
    const int bn = bx * 256;             // 0..3071 within stacked W
    const int seg = bn >> 10;            // 0=q, 1=k, 2=v
    const int cn = bn & (DD - 1);

    const float* bias = (seg == 0) ? bq : (seg == 1) ? bk : bv;
    float* C = (seg == 0) ? Cq : (seg == 1) ? Ck : Cv;

    const uint8_t* axh = g_xpack_hi + (size_t)blockIdx.y * NCHK * TILE_PK;
    const uint8_t* axl = g_xpack_lo + (size_t)blockIdx.y * NCHK * TILE_PK;
    const uint8_t* bwh = g_wpack_hi + (size_t)(bx * 2) * NCHK * TILE_PK;
    const uint8_t* bwl = g_wpack_lo + (size_t)(bx * 2) * NCHK * TILE_PK;

    const int lr = lane & 7;
    const int g = lane >> 3;                       // 0..3
    const uint32_t a_row = warp_m * 64 + (g & 1) * 8 + lr;   // + mt*16
    const uint32_t a_koff = (g >> 1) * 8;
    const uint32_t b_row = warp_n * 64 + ((lane >> 4) << 3) + lr;  // + j*16
    const uint32_t b_koff = ((lane >> 3) & 1) * 8;

    float acc[4][8][4];
#pragma unroll
    for (int i = 0; i < 4; i++)
#pragma unroll
        for (int j = 0; j < 8; j++)
#pragma unroll
            for (int r = 0; r < 4; r++) acc[i][j][r] = 0.f;

    if (tid == 0) {
#pragma unroll
        for (int s = 0; s < NSTAGE; s++)
            MBARRIER_INIT(smem_base + SM_MBAR + s * 8, 1);
    }
    __syncthreads();

    auto issue = [&](int ch) {
        const int s = ch % NSTAGE;
        const uint32_t mbar = smem_base + SM_MBAR + s * 8;
        const uint32_t sb = smem_base + s * STAGE_B;
        MBARRIER_EXPECT_TX(mbar, STAGE_B);
        cp_bulk(sb + ST_A_HI,           axh + (size_t)ch * TILE_PK, TILE_PK, mbar);
        cp_bulk(sb + ST_A_LO,           axl + (size_t)ch * TILE_PK, TILE_PK, mbar);
        cp_bulk(sb + ST_B_HI,           bwh + (size_t)ch * TILE_PK, TILE_PK, mbar);
        cp_bulk(sb + ST_B_HI + TILE_PK, bwh + (size_t)(NCHK + ch) * TILE_PK, TILE_PK, mbar);
        cp_bulk(sb + ST_B_LO,           bwl + (size_t)ch * TILE_PK, TILE_PK, mbar);
        cp_bulk(sb + ST_B_LO + TILE_PK, bwl + (size_t)(NCHK + ch) * TILE_PK, TILE_PK, mbar);
    };

    if (tid == 0) { issue(0); issue(1); }

    int s = 0, p = 0;
    for (int ch = 0; ch < NCHK; ch++) {
        MBARRIER_WAIT_PARITY(smem_base + SM_MBAR + s * 8, p);
        __syncthreads();
        if (tid == 0 && ch + 2 < NCHK) issue(ch + 2);

        const uint32_t base = smem_base + s * STAGE_B;
#pragma unroll
        for (int ks = 0; ks < 2; ks++) {
            uint32_t ahi[4][4], alo[4][4], bhi[4][4], blo[4][4];
#pragma unroll
            for (int mt = 0; mt < 4; mt++) {
                uint32_t ar = base + (a_row + mt * 16) * ROWB
                            + (ks * 16 + a_koff) * 2;
                ldm_x4(ahi[mt], ar + ST_A_HI);
                ldm_x4(alo[mt], ar + ST_A_LO);
            }
#pragma unroll
            for (int j = 0; j < 4; j++) {
                uint32_t br = base + (b_row + j * 16) * ROWB
                            + (ks * 16 + b_koff) * 2;
                ldm_x4(bhi[j], br + ST_B_HI);
                ldm_x4(blo[j], br + ST_B_LO);
            }
#pragma unroll
            for (int mt = 0; mt < 4; mt++)
#pragma unroll
                for (int nt = 0; nt < 8; nt++)
                    mma_bf16(acc[mt][nt], ahi[mt], &bhi[nt >> 1][(nt & 1) * 2]);
#pragma unroll
            for (int mt = 0; mt < 4; mt++)
#pragma unroll
                for (int nt = 0; nt < 8; nt++)
                    mma_bf16(acc[mt][nt], ahi[mt], &blo[nt >> 1][(nt & 1) * 2]);
#pragma unroll
            for (int mt = 0; mt < 4; mt++)
#pragma unroll
                for (int nt = 0; nt < 8; nt++)
                    mma_bf16(acc[mt][nt], alo[mt], &bhi[nt >> 1][(nt & 1) * 2]);
        }
        s++;
        if (s == NSTAGE) { s = 0; p ^= 1; }
    }

    const int qr = lane >> 2;           // 0..7
    const int qc = (lane & 3) * 2;      // 0,2,4,6
#pragma unroll
    for (int mt = 0; mt < 4; mt++) {
#pragma unroll
        for (int nt = 0; nt < 8; nt++) {
            const int row0 = bm + warp_m * 64 + mt * 16 + qr;
            const int col = cn + warp_n * 64 + nt * 8 + qc;
            const float2 bvv = *(const float2*)&bias[col];
            float2 v0, v1;
            v0.x = acc[mt][nt][0] + bvv.x;
            v0.y = acc[mt][nt][1] + bvv.y;
            v1.x = acc[mt][nt][2] + bvv.x;
            v1.y = acc[mt][nt][3] + bvv.y;
            const size_t o0 = (size_t)row0 * DD + col;
            const size_t o1 = (size_t)(row0 + 8) * DD + col;
            if (mul != nullptr) {
                const float2 m0 = *(const float2*)&mul[o0];
                const float2 m1 = *(const float2*)&mul[o1];
                v0.x *= m0.x; v0.y *= m0.y;
                v1.x *= m1.x; v1.y *= m1.y;
            }
            *(float2*)&C[o0] = v0;
            *(float2*)&C[o1] = v1;
        }
    }
}

// ---------------- chunked scan (g_v holds kv) --------------------------------
__global__ __launch_bounds__(256) void scan1_kernel(const float* __restrict__ decay) {
    int x = blockIdx.x * blockDim.x + threadIdx.x;   // < NCH*BB*DD
    int d = x & (DD - 1);
    int b = (x >> 10) & (BB - 1);
    int c = x >> 13;
    float dec = decay[d];
    size_t base = (size_t)b * TT * DD + (size_t)c * LCH * DD + d;
    float mem = 0.f;
#pragma unroll 4
    for (int t = 0; t < LCH; t++)
        mem = fmaf(dec, mem, g_v[base + (size_t)t * DD]);
    g_finals[((size_t)c * BB + b) * DD + d] = mem;
}

__global__ __launch_bounds__(256) void scan2_kernel(const float* __restrict__ decay) {
    int x = blockIdx.x * blockDim.x + threadIdx.x;   // < BB*DD
    int d = x & (DD - 1);
    int b = x >> 10;
    float dec = decay[d];
    float pL = dec;
#pragma unroll
    for (int i = 0; i < 7; i++) pL *= pL;            // dec^128
    float carry = 0.f;
#pragma unroll
    for (int c = 0; c < NCH; c++) {
        size_t idx = ((size_t)c * BB + b) * DD + d;
        g_carries[idx] = carry;
        carry = fmaf(pL, carry, g_finals[idx]);
    }
}

__global__ __launch_bounds__(256) void scan3_kernel(const float* __restrict__ decay,
                                                    float* __restrict__ out) {
    int x = blockIdx.x * blockDim.x + threadIdx.x;
    int d = x & (DD - 1);
    int b = (x >> 10) & (BB - 1);
    int c = x >> 13;
    float dec = decay[d];
    size_t base = (size_t)b * TT * DD + (size_t)c * LCH * DD + d;
    float mem = g_carries[((size_t)c * BB + b) * DD + d];
#pragma unroll 4
    for (int t = 0; t < LCH; t++) {
        size_t off = base + (size_t)t * DD;
        mem = fmaf(dec, mem, g_v[off]);
        out[off] = g_q[off] * mem;
    }
}

// ---------------- launch -----------------------------------------------------
extern "C" void kernel_launch(void* const* d_in, const int* in_sizes, int n_in,
                              void* d_out, int out_size) {
    const float* x     = (const float*)d_in[0];
    const float* Wq    = (const float*)d_in[1];
    const float* bq    = (const float*)d_in[2];
    const float* Wk    = (const float*)d_in[3];
    const float* bk    = (const float*)d_in[4];
    const float* Wv    = (const float*)d_in[5];
    const float* bv    = (const float*)d_in[6];
    const float* decay = (const float*)d_in[7];
    float* out = (float*)d_out;

    float *q_p, *k_p, *v_p;
    uint8_t *xh_p, *xl_p, *wh_p, *wl_p;
    cudaGetSymbolAddress((void**)&q_p, g_q);
    cudaGetSymbolAddress((void**)&k_p, g_k);
    cudaGetSymbolAddress((void**)&v_p, g_v);
    cudaGetSymbolAddress((void**)&xh_p, g_xpack_hi);
    cudaGetSymbolAddress((void**)&xl_p, g_xpack_lo);
    cudaGetSymbolAddress((void**)&wh_p, g_wpack_hi);
    cudaGetSymbolAddress((void**)&wl_p, g_wpack_lo);

    const int XN4 = MT * DD / 4;                 // 4M
    const int WN4 = DD * DD / 4;                 // 256K
    const size_t WSEG = (size_t)8 * NCHK * TILE_PK;

    // packed hi/lo splits
    split_pack_kernel<<<XN4 / 256, 256>>>(x, xh_p, xl_p, XN4);
    split_pack_kernel<<<WN4 / 256, 256>>>(Wq, wh_p + 0 * WSEG, wl_p + 0 * WSEG, WN4);
    split_pack_kernel<<<WN4 / 256, 256>>>(Wk, wh_p + 1 * WSEG, wl_p + 1 * WSEG, WN4);
    split_pack_kernel<<<WN4 / 256, 256>>>(Wv, wh_p + 2 * WSEG, wl_p + 2 * WSEG, WN4);

    const int smem_bytes = NSTAGE * STAGE_B + 64;   // 184384
    cudaFuncSetAttribute(gemm_qkv_kernel, cudaFuncAttributeMaxDynamicSharedMemorySize, smem_bytes);

    // QK GEMM: W columns 0..2047 (q and k segments), 1024 CTAs
    dim3 grid_qk(8, MT / 128);
    gemm_qkv_kernel<<<grid_qk, 256, smem_bytes>>>(bq, bk, bv, q_p, k_p, v_p,
                                                  nullptr, 0);
    // V GEMM: W columns 2048..3071, epilogue multiplies by k -> g_v holds kv
    dim3 grid_v(4, MT / 128);
    gemm_qkv_kernel<<<grid_v, 256, smem_bytes>>>(bq, bk, bv, q_p, k_p, v_p,
                                                 k_p, 8);

    // chunked scan over kv
    scan1_kernel<<<(NCH * BB * DD) / 256, 256>>>(decay);
    scan2_kernel<<<(BB * DD) / 256, 256>>>(decay);
    scan3_kernel<<<(NCH * BB * DD) / 256, 256>>>(decay, out);
}

// round 16
// speedup vs baseline: 1.3613x; 1.0240x over previous
#include <cuda_runtime.h>
#include <cuda_bf16.h>
#include <cstdint>

#define BB 8
#define TT 2048
#define DD 1024
#define MT (BB * TT)   // 16384 rows

#define TILE_PK 10240               // one packed tile: 128 rows x 80 B
#define XBLK 128                    // x row-blocks (MT/128)
#define WBLK 24                     // stacked W row-blocks (3072/128)
#define NCHK 32                     // K chunks of 32

// ---------------- scratch (__device__ globals; no allocs allowed) -----------
__device__ float g_q[(size_t)MT * DD];
__device__ float g_k[(size_t)MT * DD];
__device__ float g_v[(size_t)MT * DD];          // holds kv after fused V epilogue
__device__ uint8_t g_xpack_hi[(size_t)XBLK * NCHK * TILE_PK];   // 40 MB
__device__ uint8_t g_xpack_lo[(size_t)XBLK * NCHK * TILE_PK];
__device__ uint8_t g_wpack_hi[(size_t)WBLK * NCHK * TILE_PK];   // 7.5 MB
__device__ uint8_t g_wpack_lo[(size_t)WBLK * NCHK * TILE_PK];
// scan intermediates
#define NCH 16
#define LCH 128
__device__ float g_finals[NCH * BB * DD];

// ---------------- helpers ----------------------------------------------------
__device__ __forceinline__ uint32_t smem_to_u32(const void* p) {
    uint32_t a;
    asm("{ .reg .u64 t; cvta.to.shared.u64 t, %1; cvt.u32.u64 %0, t; }"
        : "=r"(a) : "l"(p));
    return a;
}
__device__ __forceinline__ void cp_bulk(uint32_t sdst, const void* gsrc,
                                        uint32_t bytes, uint32_t mbar) {
    asm volatile("cp.async.bulk.shared::cta.global.mbarrier::complete_tx::bytes "
                 "[%0], [%1], %2, [%3];"
                 :: "r"(sdst), "l"(gsrc), "r"(bytes), "r"(mbar) : "memory");
}
#define MBARRIER_INIT(mbar, count) \
    asm volatile("mbarrier.init.shared.b64 [%0], %1;" \
                 :: "r"((uint32_t)(mbar)), "r"((uint32_t)(count)) : "memory")
#define MBARRIER_EXPECT_TX(mbar, bytes) \
    asm volatile("mbarrier.arrive.expect_tx.shared.b64 _, [%0], %1;" \
                 :: "r"((uint32_t)(mbar)), "r"((uint32_t)(bytes)) : "memory")
#define MBARRIER_WAIT_PARITY(mbar_smem_addr, phase_parity) do { \
    uint32_t _mbar = (uint32_t)(mbar_smem_addr); \
    uint32_t _parity = (uint32_t)(phase_parity); \
    uint32_t _done; \
    asm volatile("{\n\t.reg .pred p;\n\t" \
        "mbarrier.try_wait.parity.acquire.cta.shared::cta.b64 p, [%1], %2;\n\t" \
        "selp.b32 %0, 1, 0, p;\n\t}" : "=r"(_done) : "r"(_mbar), "r"(_parity) : "memory"); \
    if (!_done) { \
        asm volatile("{\n\t.reg .pred P1;\n\t" \
            "WAIT_LOOP_%=:\n\t" \
            "mbarrier.try_wait.parity.acquire.cta.shared::cta.b64 P1, [%0], %1, 0x989680;\n\t" \
            "@P1 bra.uni WAIT_DONE_%=;\n\t" \
            "bra.uni WAIT_LOOP_%=;\n\t" \
            "WAIT_DONE_%=:\n\t}" :: "r"(_mbar), "r"(_parity) : "memory"); \
    } \
} while (0)
__device__ __forceinline__ void ldm_x4(uint32_t* r, uint32_t addr) {
    asm volatile("ldmatrix.sync.aligned.m8n8.x4.shared.b16 {%0,%1,%2,%3}, [%4];"
                 : "=r"(r[0]), "=r"(r[1]), "=r"(r[2]), "=r"(r[3]) : "r"(addr));
}
__device__ __forceinline__ void mma_bf16(float* c, const uint32_t* a, const uint32_t* b) {
    asm volatile("mma.sync.aligned.m16n8k16.row.col.f32.bf16.bf16.f32 "
                 "{%0,%1,%2,%3}, {%4,%5,%6,%7}, {%8,%9}, {%0,%1,%2,%3};"
                 : "+f"(c[0]), "+f"(c[1]), "+f"(c[2]), "+f"(c[3])
                 : "r"(a[0]), "r"(a[1]), "r"(a[2]), "r"(a[3]),
                   "r"(b[0]), "r"(b[1]));
}
// integer power (exponent < 128) by binary squaring
__device__ __forceinline__ float powi7(float b, int e) {
    float r = 1.f, p = b;
#pragma unroll
    for (int i = 0; i < 7; i++) {
        if (e & 1) r *= p;
        p *= p;
        e >>= 1;
    }
    return r;
}

// ---------------- merged split: x + Wq + Wk + Wv in one launch ---------------
// blocks [0, XB): x ; [XB, XB+WB): Wq ; [+WB): Wk ; [+2WB): Wv
#define XSPB (MT * DD / 4 / 256)    // 16384 blocks for x
#define WSPB (DD * DD / 4 / 256)    // 1024 blocks per W
__global__ __launch_bounds__(256) void split_all_kernel(
    const float* __restrict__ x, const float* __restrict__ Wq,
    const float* __restrict__ Wk, const float* __restrict__ Wv,
    uint8_t* __restrict__ xhi, uint8_t* __restrict__ xlo,
    uint8_t* __restrict__ whi, uint8_t* __restrict__ wlo) {
    const size_t WSEG = (size_t)8 * NCHK * TILE_PK;
    const float* src;
    uint8_t *hi, *lo;
    int i;
    int bid = blockIdx.x;
    if (bid < XSPB) {
        src = x; hi = xhi; lo = xlo;
        i = bid * 256 + threadIdx.x;
    } else {
        int w = (bid - XSPB) / WSPB;            // 0..2
        src = (w == 0) ? Wq : (w == 1) ? Wk : Wv;
        hi = whi + (size_t)w * WSEG;
        lo = wlo + (size_t)w * WSEG;
        i = ((bid - XSPB) % WSPB) * 256 + threadIdx.x;
    }
    int r = i >> 8;               // row (256 float4 per row)
    int c = (i & 255) << 2;       // starting col
    float4 v = ((const float4*)src)[i];
    __nv_bfloat16 h[4], l[4];
    float f[4] = {v.x, v.y, v.z, v.w};
#pragma unroll
    for (int j = 0; j < 4; j++) {
        h[j] = __float2bfloat16_rn(f[j]);
        l[j] = __float2bfloat16_rn(f[j] - __bfloat162float(h[j]));
    }
    size_t off = (size_t)((r >> 7) * NCHK + (c >> 5)) * TILE_PK
               + (size_t)(r & 127) * 80 + (size_t)((c & 31) << 1);
    *(uint2*)(hi + off) = *(uint2*)h;
    *(uint2*)(lo + off) = *(uint2*)l;
}

// ---------------- fused QKV HMMA bf16 split GEMM, bulk-async loads -----------
// mul != nullptr => V pass: epilogue multiplies by mul (k) giving kv, AND
// computes the scan chunk-final sum_t dec^(127-t) * kv_t into g_finals.
#define ROWB 80
#define ST_A_HI 0
#define ST_A_LO (128 * ROWB)               // 10240
#define ST_B_HI (2 * 128 * ROWB)           // 20480 (2 tiles)
#define ST_B_LO (ST_B_HI + 256 * ROWB)     // 40960 (2 tiles)
#define STAGE_B (ST_B_LO + 256 * ROWB)     // 61440
#define NSTAGE 3
#define SM_MBAR (NSTAGE * STAGE_B)         // mbarriers after stages

__global__ __launch_bounds__(256, 1) void gemm_qkv_kernel(
    const float* __restrict__ bq, const float* __restrict__ bk,
    const float* __restrict__ bv,
    float* __restrict__ Cq, float* __restrict__ Ck, float* __restrict__ Cv,
    const float* __restrict__ mul, const float* __restrict__ decay, int xoff) {
    extern __shared__ char smem[];
    const uint32_t smem_base = smem_to_u32(smem);
    const int tid = threadIdx.x;
    const int wid = tid >> 5;
    const int lane = tid & 31;
    const int warp_m = wid & 1;          // 2 warps in M (64 rows each)
    const int warp_n = wid >> 1;         // 4 warps in N (64 cols each)
    const int bx = blockIdx.x + xoff;
    const int bm = blockIdx.y * 128;
    const int bn = bx * 256;             // 0..3071 within stacked W
    const int seg = bn >> 10;            // 0=q, 1=k, 2=v
    const int cn = bn & (DD - 1);

    const float* bias = (seg == 0) ? bq : (seg == 1) ? bk : bv;
    float* C = (seg == 0) ? Cq : (seg == 1) ? Ck : Cv;

    const uint8_t* axh = g_xpack_hi + (size_t)blockIdx.y * NCHK * TILE_PK;
    const uint8_t* axl = g_xpack_lo + (size_t)blockIdx.y * NCHK * TILE_PK;
    const uint8_t* bwh = g_wpack_hi + (size_t)(bx * 2) * NCHK * TILE_PK;
    const uint8_t* bwl = g_wpack_lo + (size_t)(bx * 2) * NCHK * TILE_PK;

    const int lr = lane & 7;
    const int g = lane >> 3;                       // 0..3
    const uint32_t a_row = warp_m * 64 + (g & 1) * 8 + lr;   // + mt*16
    const uint32_t a_koff = (g >> 1) * 8;
    const uint32_t b_row = warp_n * 64 + ((lane >> 4) << 3) + lr;  // + j*16
    const uint32_t b_koff = ((lane >> 3) & 1) * 8;

    float acc[4][8][4];
#pragma unroll
    for (int i = 0; i < 4; i++)
#pragma unroll
        for (int j = 0; j < 8; j++)
#pragma unroll
            for (int r = 0; r < 4; r++) acc[i][j][r] = 0.f;

    if (tid == 0) {
#pragma unroll
        for (int s = 0; s < NSTAGE; s++)
            MBARRIER_INIT(smem_base + SM_MBAR + s * 8, 1);
    }
    __syncthreads();

    auto issue = [&](int ch) {
        const int s = ch % NSTAGE;
        const uint32_t mbar = smem_base + SM_MBAR + s * 8;
        const uint32_t sb = smem_base + s * STAGE_B;
        MBARRIER_EXPECT_TX(mbar, STAGE_B);
        cp_bulk(sb + ST_A_HI,           axh + (size_t)ch * TILE_PK, TILE_PK, mbar);
        cp_bulk(sb + ST_A_LO,           axl + (size_t)ch * TILE_PK, TILE_PK, mbar);
        cp_bulk(sb + ST_B_HI,           bwh + (size_t)ch * TILE_PK, TILE_PK, mbar);
        cp_bulk(sb + ST_B_HI + TILE_PK, bwh + (size_t)(NCHK + ch) * TILE_PK, TILE_PK, mbar);
        cp_bulk(sb + ST_B_LO,           bwl + (size_t)ch * TILE_PK, TILE_PK, mbar);
        cp_bulk(sb + ST_B_LO + TILE_PK, bwl + (size_t)(NCHK + ch) * TILE_PK, TILE_PK, mbar);
    };

    if (tid == 0) { issue(0); issue(1); }

    int s = 0, p = 0;
    for (int ch = 0; ch < NCHK; ch++) {
        MBARRIER_WAIT_PARITY(smem_base + SM_MBAR + s * 8, p);
        __syncthreads();
        if (tid == 0 && ch + 2 < NCHK) issue(ch + 2);

        const uint32_t base = smem_base + s * STAGE_B;
#pragma unroll
        for (int ks = 0; ks < 2; ks++) {
            uint32_t ahi[4][4], alo[4][4], bhi[4][4], blo[4][4];
#pragma unroll
            for (int mt = 0; mt < 4; mt++) {
                uint32_t ar = base + (a_row + mt * 16) * ROWB
                            + (ks * 16 + a_koff) * 2;
                ldm_x4(ahi[mt], ar + ST_A_HI);
                ldm_x4(alo[mt], ar + ST_A_LO);
            }
#pragma unroll
            for (int j = 0; j < 4; j++) {
                uint32_t br = base + (b_row + j * 16) * ROWB
                            + (ks * 16 + b_koff) * 2;
                ldm_x4(bhi[j], br + ST_B_HI);
                ldm_x4(blo[j], br + ST_B_LO);
            }
#pragma unroll
            for (int mt = 0; mt < 4; mt++)
#pragma unroll
                for (int nt = 0; nt < 8; nt++)
                    mma_bf16(acc[mt][nt], ahi[mt], &bhi[nt >> 1][(nt & 1) * 2]);
#pragma unroll
            for (int mt = 0; mt < 4; mt++)
#pragma unroll
                for (int nt = 0; nt < 8; nt++)
                    mma_bf16(acc[mt][nt], ahi[mt], &blo[nt >> 1][(nt & 1) * 2]);
#pragma unroll
            for (int mt = 0; mt < 4; mt++)
#pragma unroll
                for (int nt = 0; nt < 8; nt++)
                    mma_bf16(acc[mt][nt], alo[mt], &bhi[nt >> 1][(nt & 1) * 2]);
        }
        s++;
        if (s == NSTAGE) { s = 0; p ^= 1; }
    }

    const int qr = lane >> 2;           // 0..7
    const int qc = (lane & 3) * 2;      // 0,2,4,6

    if (mul == nullptr) {
        // plain epilogue: bias + store
#pragma unroll
        for (int mt = 0; mt < 4; mt++) {
#pragma unroll
            for (int nt = 0; nt < 8; nt++) {
                const int row0 = bm + warp_m * 64 + mt * 16 + qr;
                const int col = cn + warp_n * 64 + nt * 8 + qc;
                const float2 bvv = *(const float2*)&bias[col];
                float2 v0, v1;
                v0.x = acc[mt][nt][0] + bvv.x;
                v0.y = acc[mt][nt][1] + bvv.y;
                v1.x = acc[mt][nt][2] + bvv.x;
                v1.y = acc[mt][nt][3] + bvv.y;
                *(float2*)&C[(size_t)row0 * DD + col] = v0;
                *(float2*)&C[(size_t)(row0 + 8) * DD + col] = v1;
            }
        }
    } else {
        // V epilogue: kv = (acc + bias) * k, store, AND chunk-final reduction.
        // finals(c,b,col) = sum_t dec^(127-t) * kv_t ; this CTA covers exactly
        // one (b, chunk): rows bm..bm+127 with local t = row - bm.
        const int b_idx = bm >> 11;
        const int c_idx = (bm >> 7) & (NCH - 1);
        const int E0 = 127 - warp_m * 64 - qr;     // exponent for mt=0 row
        float sxa[8], sya[8];
#pragma unroll
        for (int nt = 0; nt < 8; nt++) {
            const int col = cn + warp_n * 64 + nt * 8 + qc;
            const float2 bvv = *(const float2*)&bias[col];
            const float2 dc = *(const float2*)&decay[col];
            float wx = powi7(dc.x, E0);
            float wy = powi7(dc.y, E0);
            const float ivx = 1.f / dc.x, ivy = 1.f / dc.y;
            float i8x = ivx * ivx; i8x *= i8x; i8x *= i8x;   // ivx^8
            float i8y = ivy * ivy; i8y *= i8y; i8y *= i8y;
            const float i16x = i8x * i8x, i16y = i8y * i8y;
            float sx = 0.f, sy = 0.f;
#pragma unroll
            for (int mt = 0; mt < 4; mt++) {
                const int row0 = bm + warp_m * 64 + mt * 16 + qr;
                const size_t o0 = (size_t)row0 * DD + col;
                const size_t o1 = (size_t)(row0 + 8) * DD + col;
                const float2 m0 = *(const float2*)&mul[o0];
                const float2 m1 = *(const float2*)&mul[o1];
                float2 v0, v1;
                v0.x = (acc[mt][nt][0] + bvv.x) * m0.x;
                v0.y = (acc[mt][nt][1] + bvv.y) * m0.y;
                v1.x = (acc[mt][nt][2] + bvv.x) * m1.x;
                v1.y = (acc[mt][nt][3] + bvv.y) * m1.y;
                *(float2*)&C[o0] = v0;
                *(float2*)&C[o1] = v1;
                sx += wx * v0.x + (wx * i8x) * v1.x;
                sy += wy * v0.y + (wy * i8y) * v1.y;
                wx *= i16x;
                wy *= i16y;
            }
            sxa[nt] = sx;
            sya[nt] = sy;
        }
        // reduce over the 8 lanes sharing each column (xor bits 2..4)
#pragma unroll
        for (int nt = 0; nt < 8; nt++) {
#pragma unroll
            for (int off = 4; off < 32; off <<= 1) {
                sxa[nt] += __shfl_xor_sync(0xffffffffu, sxa[nt], off);
                sya[nt] += __shfl_xor_sync(0xffffffffu, sya[nt], off);
            }
        }
        // cross warp_m reduction via smem (stage memory is free now)
        float* red = (float*)smem;     // [warp_n][nt][lane4][2] = 256 floats
        __syncthreads();
        if (warp_m == 1 && lane < 4) {
#pragma unroll
            for (int nt = 0; nt < 8; nt++) {
                red[((warp_n * 8 + nt) * 4 + lane) * 2 + 0] = sxa[nt];
                red[((warp_n * 8 + nt) * 4 + lane) * 2 + 1] = sya[nt];
            }
        }
        __syncthreads();
        if (warp_m == 0 && lane < 4) {
#pragma unroll
            for (int nt = 0; nt < 8; nt++) {
                const float fx = sxa[nt] + red[((warp_n * 8 + nt) * 4 + lane) * 2 + 0];
                const float fy = sya[nt] + red[((warp_n * 8 + nt) * 4 + lane) * 2 + 1];
                const int col = cn + warp_n * 64 + nt * 8 + lane * 2;
                const size_t fo = ((size_t)c_idx * BB + b_idx) * DD + col;
                g_finals[fo] = fx;
                g_finals[fo + 1] = fy;
            }
        }
    }
}

// ---------------- scan: carry from finals + full chunk scan ------------------
__global__ __launch_bounds__(256) void scan3_kernel(const float* __restrict__ decay,
                                                    float* __restrict__ out) {
    int x = blockIdx.x * blockDim.x + threadIdx.x;
    int d = x & (DD - 1);
    int b = (x >> 10) & (BB - 1);
    int c = x >> 13;
    float dec = decay[d];
    float pL = dec;
#pragma unroll
    for (int i = 0; i < 7; i++) pL *= pL;            // dec^128

    // carry = scan2 recurrence over predecessor chunk finals
    float carry = 0.f;
    for (int cc = 0; cc < c; cc++)
        carry = fmaf(pL, carry, g_finals[((size_t)cc * BB + b) * DD + d]);

    size_t base = (size_t)b * TT * DD + (size_t)c * LCH * DD + d;
    float mem = carry;
#pragma unroll 4
    for (int t = 0; t < LCH; t++) {
        size_t off = base + (size_t)t * DD;
        mem = fmaf(dec, mem, g_v[off]);
        out[off] = g_q[off] * mem;
    }
}

// ---------------- launch -----------------------------------------------------
extern "C" void kernel_launch(void* const* d_in, const int* in_sizes, int n_in,
                              void* d_out, int out_size) {
    const float* x     = (const float*)d_in[0];
    const float* Wq    = (const float*)d_in[1];
    const float* bq    = (const float*)d_in[2];
    const float* Wk    = (const float*)d_in[3];
    const float* bk    = (const float*)d_in[4];
    const float* Wv    = (const float*)d_in[5];
    const float* bv    = (const float*)d_in[6];
    const float* decay = (const float*)d_in[7];
    float* out = (float*)d_out;

    float *q_p, *k_p, *v_p;
    uint8_t *xh_p, *xl_p, *wh_p, *wl_p;
    cudaGetSymbolAddress((void**)&q_p, g_q);
    cudaGetSymbolAddress((void**)&k_p, g_k);
    cudaGetSymbolAddress((void**)&v_p, g_v);
    cudaGetSymbolAddress((void**)&xh_p, g_xpack_hi);
    cudaGetSymbolAddress((void**)&xl_p, g_xpack_lo);
    cudaGetSymbolAddress((void**)&wh_p, g_wpack_hi);
    cudaGetSymbolAddress((void**)&wl_p, g_wpack_lo);

    // merged hi/lo splits (x + Wq + Wk + Wv), one launch
    split_all_kernel<<<XSPB + 3 * WSPB, 256>>>(x, Wq, Wk, Wv,
                                               xh_p, xl_p, wh_p, wl_p);

    const int smem_bytes = NSTAGE * STAGE_B + 64;   // 184384
    cudaFuncSetAttribute(gemm_qkv_kernel, cudaFuncAttributeMaxDynamicSharedMemorySize, smem_bytes);

    // QK GEMM: W columns 0..2047 (q and k segments), 1024 CTAs
    dim3 grid_qk(8, MT / 128);
    gemm_qkv_kernel<<<grid_qk, 256, smem_bytes>>>(bq, bk, bv, q_p, k_p, v_p,
                                                  nullptr, decay, 0);
    // V GEMM: W columns 2048..3071; epilogue stores kv AND chunk finals
    dim3 grid_v(4, MT / 128);
    gemm_qkv_kernel<<<grid_v, 256, smem_bytes>>>(bq, bk, bv, q_p, k_p, v_p,
                                                 k_p, decay, 8);

    // single scan pass (carry computed inline from finals)
    scan3_kernel<<<(NCH * BB * DD) / 256, 256>>>(decay, out);
}

// round 17
// speedup vs baseline: 1.3727x; 1.0083x over previous
#include <cuda_runtime.h>
#include <cuda_bf16.h>
#include <cstdint>

#define BB 8
#define TT 2048
#define DD 1024
#define MT (BB * TT)   // 16384 rows

#define TILE_PK 10240               // one packed tile: 128 rows x 80 B
#define XBLK 128                    // x row-blocks (MT/128)
#define WBLK 24                     // stacked W row-blocks (3072/128)
#define NCHK 32                     // K chunks of 32

// ---------------- scratch (__device__ globals; no allocs allowed) -----------
__device__ float g_q[(size_t)MT * DD];
__device__ float g_k[(size_t)MT * DD];
__device__ float g_v[(size_t)MT * DD];          // holds kv after fused V epilogue
__device__ uint8_t g_xpack_hi[(size_t)XBLK * NCHK * TILE_PK];   // 40 MB
__device__ uint8_t g_xpack_lo[(size_t)XBLK * NCHK * TILE_PK];
__device__ uint8_t g_wpack_hi[(size_t)WBLK * NCHK * TILE_PK];   // 7.5 MB
__device__ uint8_t g_wpack_lo[(size_t)WBLK * NCHK * TILE_PK];
// scan state: finals at 64-row granularity
#define NCH2 32
#define LCH2 64
__device__ float g_finals[NCH2 * BB * DD];

// ---------------- helpers ----------------------------------------------------
__device__ __forceinline__ uint32_t smem_to_u32(const void* p) {
    uint32_t a;
    asm("{ .reg .u64 t; cvta.to.shared.u64 t, %1; cvt.u32.u64 %0, t; }"
        : "=r"(a) : "l"(p));
    return a;
}
__device__ __forceinline__ void cp_bulk(uint32_t sdst, const void* gsrc,
                                        uint32_t bytes, uint32_t mbar) {
    asm volatile("cp.async.bulk.shared::cta.global.mbarrier::complete_tx::bytes "
                 "[%0], [%1], %2, [%3];"
                 :: "r"(sdst), "l"(gsrc), "r"(bytes), "r"(mbar) : "memory");
}
#define MBARRIER_INIT(mbar, count) \
    asm volatile("mbarrier.init.shared.b64 [%0], %1;" \
                 :: "r"((uint32_t)(mbar)), "r"((uint32_t)(count)) : "memory")
#define MBARRIER_EXPECT_TX(mbar, bytes) \
    asm volatile("mbarrier.arrive.expect_tx.shared.b64 _, [%0], %1;" \
                 :: "r"((uint32_t)(mbar)), "r"((uint32_t)(bytes)) : "memory")
#define MBARRIER_WAIT_PARITY(mbar_smem_addr, phase_parity) do { \
    uint32_t _mbar = (uint32_t)(mbar_smem_addr); \
    uint32_t _parity = (uint32_t)(phase_parity); \
    uint32_t _done; \
    asm volatile("{\n\t.reg .pred p;\n\t" \
        "mbarrier.try_wait.parity.acquire.cta.shared::cta.b64 p, [%1], %2;\n\t" \
        "selp.b32 %0, 1, 0, p;\n\t}" : "=r"(_done) : "r"(_mbar), "r"(_parity) : "memory"); \
    if (!_done) { \
        asm volatile("{\n\t.reg .pred P1;\n\t" \
            "WAIT_LOOP_%=:\n\t" \
            "mbarrier.try_wait.parity.acquire.cta.shared::cta.b64 P1, [%0], %1, 0x989680;\n\t" \
            "@P1 bra.uni WAIT_DONE_%=;\n\t" \
            "bra.uni WAIT_LOOP_%=;\n\t" \
            "WAIT_DONE_%=:\n\t}" :: "r"(_mbar), "r"(_parity) : "memory"); \
    } \
} while (0)
__device__ __forceinline__ void ldm_x4(uint32_t* r, uint32_t addr) {
    asm volatile("ldmatrix.sync.aligned.m8n8.x4.shared.b16 {%0,%1,%2,%3}, [%4];"
                 : "=r"(r[0]), "=r"(r[1]), "=r"(r[2]), "=r"(r[3]) : "r"(addr));
}
__device__ __forceinline__ void mma_bf16(float* c, const uint32_t* a, const uint32_t* b) {
    asm volatile("mma.sync.aligned.m16n8k16.row.col.f32.bf16.bf16.f32 "
                 "{%0,%1,%2,%3}, {%4,%5,%6,%7}, {%8,%9}, {%0,%1,%2,%3};"
                 : "+f"(c[0]), "+f"(c[1]), "+f"(c[2]), "+f"(c[3])
                 : "r"(a[0]), "r"(a[1]), "r"(a[2]), "r"(a[3]),
                   "r"(b[0]), "r"(b[1]));
}
// integer power (exponent < 128) by binary squaring
__device__ __forceinline__ float powi7(float b, int e) {
    float r = 1.f, p = b;
#pragma unroll
    for (int i = 0; i < 7; i++) {
        if (e & 1) r *= p;
        p *= p;
        e >>= 1;
    }
    return r;
}

// ---------------- merged split: x + Wq + Wk + Wv in one launch ---------------
#define XSPB (MT * DD / 4 / 256)    // 16384 blocks for x
#define WSPB (DD * DD / 4 / 256)    // 1024 blocks per W
__global__ __launch_bounds__(256) void split_all_kernel(
    const float* __restrict__ x, const float* __restrict__ Wq,
    const float* __restrict__ Wk, const float* __restrict__ Wv,
    uint8_t* __restrict__ xhi, uint8_t* __restrict__ xlo,
    uint8_t* __restrict__ whi, uint8_t* __restrict__ wlo) {
    const size_t WSEG = (size_t)8 * NCHK * TILE_PK;
    const float* src;
    uint8_t *hi, *lo;
    int i;
    int bid = blockIdx.x;
    if (bid < XSPB) {
        src = x; hi = xhi; lo = xlo;
        i = bid * 256 + threadIdx.x;
    } else {
        int w = (bid - XSPB) / WSPB;            // 0..2
        src = (w == 0) ? Wq : (w == 1) ? Wk : Wv;
        hi = whi + (size_t)w * WSEG;
        lo = wlo + (size_t)w * WSEG;
        i = ((bid - XSPB) % WSPB) * 256 + threadIdx.x;
    }
    int r = i >> 8;               // row (256 float4 per row)
    int c = (i & 255) << 2;       // starting col
    float4 v = ((const float4*)src)[i];
    __nv_bfloat16 h[4], l[4];
    float f[4] = {v.x, v.y, v.z, v.w};
#pragma unroll
    for (int j = 0; j < 4; j++) {
        h[j] = __float2bfloat16_rn(f[j]);
        l[j] = __float2bfloat16_rn(f[j] - __bfloat162float(h[j]));
    }
    size_t off = (size_t)((r >> 7) * NCHK + (c >> 5)) * TILE_PK
               + (size_t)(r & 127) * 80 + (size_t)((c & 31) << 1);
    *(uint2*)(hi + off) = *(uint2*)h;
    *(uint2*)(lo + off) = *(uint2*)l;
}

// ---------------- fused QKV HMMA bf16 split GEMM, bulk-async loads -----------
#define ROWB 80
#define ST_A_HI 0
#define ST_A_LO (128 * ROWB)               // 10240
#define ST_B_HI (2 * 128 * ROWB)           // 20480 (2 tiles)
#define ST_B_LO (ST_B_HI + 256 * ROWB)     // 40960 (2 tiles)
#define STAGE_B (ST_B_LO + 256 * ROWB)     // 61440
#define NSTAGE 3
#define SM_MBAR (NSTAGE * STAGE_B)         // mbarriers after stages

__global__ __launch_bounds__(256, 1) void gemm_qkv_kernel(
    const float* __restrict__ bq, const float* __restrict__ bk,
    const float* __restrict__ bv,
    float* __restrict__ Cq, float* __restrict__ Ck, float* __restrict__ Cv,
    const float* __restrict__ mul, const float* __restrict__ decay, int xoff) {
    extern __shared__ char smem[];
    const uint32_t smem_base = smem_to_u32(smem);
    const int tid = threadIdx.x;
    const int wid = tid >> 5;
    const int lane = tid & 31;
    const int warp_m = wid & 1;          // 2 warps in M (64 rows each)
    const int warp_n = wid >> 1;         // 4 warps in N (64 cols each)
    const int bx = blockIdx.x + xoff;
    const int bm = blockIdx.y * 128;
    const int bn = bx * 256;             // 0..3071 within stacked W
    const int seg = bn >> 10;            // 0=q, 1=k, 2=v
    const int cn = bn & (DD - 1);

    const float* bias = (seg == 0) ? bq : (seg == 1) ? bk : bv;
    float* C = (seg == 0) ? Cq : (seg == 1) ? Ck : Cv;

    const uint8_t* axh = g_xpack_hi + (size_t)blockIdx.y * NCHK * TILE_PK;
    const uint8_t* axl = g_xpack_lo + (size_t)blockIdx.y * NCHK * TILE_PK;
    const uint8_t* bwh = g_wpack_hi + (size_t)(bx * 2) * NCHK * TILE_PK;
    const uint8_t* bwl = g_wpack_lo + (size_t)(bx * 2) * NCHK * TILE_PK;

    const int lr = lane & 7;
    const int g = lane >> 3;                       // 0..3
    const uint32_t a_row = warp_m * 64 + (g & 1) * 8 + lr;   // + mt*16
    const uint32_t a_koff = (g >> 1) * 8;
    const uint32_t b_row = warp_n * 64 + ((lane >> 4) << 3) + lr;  // + j*16
    const uint32_t b_koff = ((lane >> 3) & 1) * 8;

    float acc[4][8][4];
#pragma unroll
    for (int i = 0; i < 4; i++)
#pragma unroll
        for (int j = 0; j < 8; j++)
#pragma unroll
            for (int r = 0; r < 4; r++) acc[i][j][r] = 0.f;

    if (tid == 0) {
#pragma unroll
        for (int s = 0; s < NSTAGE; s++)
            MBARRIER_INIT(smem_base + SM_MBAR + s * 8, 1);
    }
    __syncthreads();

    auto issue = [&](int ch) {
        const int s = ch % NSTAGE;
        const uint32_t mbar = smem_base + SM_MBAR + s * 8;
        const uint32_t sb = smem_base + s * STAGE_B;
        MBARRIER_EXPECT_TX(mbar, STAGE_B);
        cp_bulk(sb + ST_A_HI,           axh + (size_t)ch * TILE_PK, TILE_PK, mbar);
        cp_bulk(sb + ST_A_LO,           axl + (size_t)ch * TILE_PK, TILE_PK, mbar);
        cp_bulk(sb + ST_B_HI,           bwh + (size_t)ch * TILE_PK, TILE_PK, mbar);
        cp_bulk(sb + ST_B_HI + TILE_PK, bwh + (size_t)(NCHK + ch) * TILE_PK, TILE_PK, mbar);
        cp_bulk(sb + ST_B_LO,           bwl + (size_t)ch * TILE_PK, TILE_PK, mbar);
        cp_bulk(sb + ST_B_LO + TILE_PK, bwl + (size_t)(NCHK + ch) * TILE_PK, TILE_PK, mbar);
    };

    if (tid == 0) { issue(0); issue(1); }

    int s = 0, p = 0;
    for (int ch = 0; ch < NCHK; ch++) {
        // sync first (guards overwrite of the stage consumed 1 iter ago),
        // then issue ch+2 BEFORE blocking on the current stage's barrier.
        __syncthreads();
        if (tid == 0 && ch + 2 < NCHK) issue(ch + 2);
        MBARRIER_WAIT_PARITY(smem_base + SM_MBAR + s * 8, p);

        const uint32_t base = smem_base + s * STAGE_B;
#pragma unroll
        for (int ks = 0; ks < 2; ks++) {
            uint32_t ahi[4][4], alo[4][4], bhi[4][4], blo[4][4];
#pragma unroll
            for (int mt = 0; mt < 4; mt++) {
                uint32_t ar = base + (a_row + mt * 16) * ROWB
                            + (ks * 16 + a_koff) * 2;
                ldm_x4(ahi[mt], ar + ST_A_HI);
                ldm_x4(alo[mt], ar + ST_A_LO);
            }
#pragma unroll
            for (int j = 0; j < 4; j++) {
                uint32_t br = base + (b_row + j * 16) * ROWB
                            + (ks * 16 + b_koff) * 2;
                ldm_x4(bhi[j], br + ST_B_HI);
                ldm_x4(blo[j], br + ST_B_LO);
            }
#pragma unroll
            for (int mt = 0; mt < 4; mt++)
#pragma unroll
                for (int nt = 0; nt < 8; nt++)
                    mma_bf16(acc[mt][nt], ahi[mt], &bhi[nt >> 1][(nt & 1) * 2]);
#pragma unroll
            for (int mt = 0; mt < 4; mt++)
#pragma unroll
                for (int nt = 0; nt < 8; nt++)
                    mma_bf16(acc[mt][nt], ahi[mt], &blo[nt >> 1][(nt & 1) * 2]);
#pragma unroll
            for (int mt = 0; mt < 4; mt++)
#pragma unroll
                for (int nt = 0; nt < 8; nt++)
                    mma_bf16(acc[mt][nt], alo[mt], &bhi[nt >> 1][(nt & 1) * 2]);
        }
        s++;
        if (s == NSTAGE) { s = 0; p ^= 1; }
    }

    const int qr = lane >> 2;           // 0..7
    const int qc = (lane & 3) * 2;      // 0,2,4,6

    if (mul == nullptr) {
        // plain epilogue: bias + store
#pragma unroll
        for (int mt = 0; mt < 4; mt++) {
#pragma unroll
            for (int nt = 0; nt < 8; nt++) {
                const int row0 = bm + warp_m * 64 + mt * 16 + qr;
                const int col = cn + warp_n * 64 + nt * 8 + qc;
                const float2 bvv = *(const float2*)&bias[col];
                float2 v0, v1;
                v0.x = acc[mt][nt][0] + bvv.x;
                v0.y = acc[mt][nt][1] + bvv.y;
                v1.x = acc[mt][nt][2] + bvv.x;
                v1.y = acc[mt][nt][3] + bvv.y;
                *(float2*)&C[(size_t)row0 * DD + col] = v0;
                *(float2*)&C[(size_t)(row0 + 8) * DD + col] = v1;
            }
        }
    } else {
        // V epilogue: kv = (acc + bias) * k, store, AND 64-row sub-chunk final:
        // finals(c2,b,col) = sum_{t=0..63} dec^(63-t) * kv_t, where this
        // warp_m group covers exactly rows bm + warp_m*64 + [0,64).
        const int b_idx = bm >> 11;
        const int c2 = ((bm & 2047) >> 6) + warp_m;   // sub-chunk 0..31
        const int E0 = 63 - qr;                       // exponent for mt=0 row
        float sxa[8], sya[8];
#pragma unroll
        for (int nt = 0; nt < 8; nt++) {
            const int col = cn + warp_n * 64 + nt * 8 + qc;
            const float2 bvv = *(const float2*)&bias[col];
            const float2 dc = *(const float2*)&decay[col];
            float wx = powi7(dc.x, E0);
            float wy = powi7(dc.y, E0);
            const float ivx = 1.f / dc.x, ivy = 1.f / dc.y;
            float i8x = ivx * ivx; i8x *= i8x; i8x *= i8x;   // ivx^8
            float i8y = ivy * ivy; i8y *= i8y; i8y *= i8y;
            const float i16x = i8x * i8x, i16y = i8y * i8y;
            float sx = 0.f, sy = 0.f;
#pragma unroll
            for (int mt = 0; mt < 4; mt++) {
                const int row0 = bm + warp_m * 64 + mt * 16 + qr;
                const size_t o0 = (size_t)row0 * DD + col;
                const size_t o1 = (size_t)(row0 + 8) * DD + col;
                const float2 m0 = *(const float2*)&mul[o0];
                const float2 m1 = *(const float2*)&mul[o1];
                float2 v0, v1;
                v0.x = (acc[mt][nt][0] + bvv.x) * m0.x;
                v0.y = (acc[mt][nt][1] + bvv.y) * m0.y;
                v1.x = (acc[mt][nt][2] + bvv.x) * m1.x;
                v1.y = (acc[mt][nt][3] + bvv.y) * m1.y;
                *(float2*)&C[o0] = v0;
                *(float2*)&C[o1] = v1;
                sx += wx * v0.x + (wx * i8x) * v1.x;
                sy += wy * v0.y + (wy * i8y) * v1.y;
                wx *= i16x;
                wy *= i16y;
            }
            sxa[nt] = sx;
            sya[nt] = sy;
        }
        // reduce over the 8 lanes sharing each column (xor bits 2..4)
#pragma unroll
        for (int nt = 0; nt < 8; nt++) {
#pragma unroll
            for (int off = 4; off < 32; off <<= 1) {
                sxa[nt] += __shfl_xor_sync(0xffffffffu, sxa[nt], off);
                sya[nt] += __shfl_xor_sync(0xffffffffu, sya[nt], off);
            }
        }
        // each warp writes its own 64-row sub-chunk finals (no cross-warp hop)
        if (lane < 4) {
#pragma unroll
            for (int nt = 0; nt < 8; nt++) {
                const int col = cn + warp_n * 64 + nt * 8 + lane * 2;
                const size_t fo = ((size_t)c2 * BB + b_idx) * DD + col;
                g_finals[fo] = sxa[nt];
                g_finals[fo + 1] = sya[nt];
            }
        }
    }
}

// ---------------- scan: carry from 64-granularity finals + chunk scan --------
__global__ __launch_bounds__(256) void scan3_kernel(const float* __restrict__ decay,
                                                    float* __restrict__ out) {
    int x = blockIdx.x * blockDim.x + threadIdx.x;   // < NCH2*BB*DD
    int d = x & (DD - 1);
    int b = (x >> 10) & (BB - 1);
    int c2 = x >> 13;
    float dec = decay[d];
    float pL = dec;
#pragma unroll
    for (int i = 0; i < 6; i++) pL *= pL;            // dec^64

    // carry over predecessor sub-chunk finals
    float carry = 0.f;
    for (int cc = 0; cc < c2; cc++)
        carry = fmaf(pL, carry, g_finals[((size_t)cc * BB + b) * DD + d]);

    size_t base = (size_t)b * TT * DD + (size_t)c2 * LCH2 * DD + d;
    float mem = carry;
#pragma unroll 4
    for (int t = 0; t < LCH2; t++) {
        size_t off = base + (size_t)t * DD;
        mem = fmaf(dec, mem, g_v[off]);
        out[off] = g_q[off] * mem;
    }
}

// ---------------- launch -----------------------------------------------------
extern "C" void kernel_launch(void* const* d_in, const int* in_sizes, int n_in,
                              void* d_out, int out_size) {
    const float* x     = (const float*)d_in[0];
    const float* Wq    = (const float*)d_in[1];
    const float* bq    = (const float*)d_in[2];
    const float* Wk    = (const float*)d_in[3];
    const float* bk    = (const float*)d_in[4];
    const float* Wv    = (const float*)d_in[5];
    const float* bv    = (const float*)d_in[6];
    const float* decay = (const float*)d_in[7];
    float* out = (float*)d_out;

    float *q_p, *k_p, *v_p;
    uint8_t *xh_p, *xl_p, *wh_p, *wl_p;
    cudaGetSymbolAddress((void**)&q_p, g_q);
    cudaGetSymbolAddress((void**)&k_p, g_k);
    cudaGetSymbolAddress((void**)&v_p, g_v);
    cudaGetSymbolAddress((void**)&xh_p, g_xpack_hi);
    cudaGetSymbolAddress((void**)&xl_p, g_xpack_lo);
    cudaGetSymbolAddress((void**)&wh_p, g_wpack_hi);
    cudaGetSymbolAddress((void**)&wl_p, g_wpack_lo);

    // merged hi/lo splits (x + Wq + Wk + Wv), one launch
    split_all_kernel<<<XSPB + 3 * WSPB, 256>>>(x, Wq, Wk, Wv,
                                               xh_p, xl_p, wh_p, wl_p);

    const int smem_bytes = NSTAGE * STAGE_B + 64;   // 184384
    cudaFuncSetAttribute(gemm_qkv_kernel, cudaFuncAttributeMaxDynamicSharedMemorySize, smem_bytes);

    // QK GEMM: W columns 0..2047 (q and k segments), 1024 CTAs
    dim3 grid_qk(8, MT / 128);
    gemm_qkv_kernel<<<grid_qk, 256, smem_bytes>>>(bq, bk, bv, q_p, k_p, v_p,
                                                  nullptr, decay, 0);
    // V GEMM: W columns 2048..3071; epilogue stores kv AND 64-row finals
    dim3 grid_v(4, MT / 128);
    gemm_qkv_kernel<<<grid_v, 256, smem_bytes>>>(bq, bk, bv, q_p, k_p, v_p,
                                                 k_p, decay, 8);

    // single scan pass (carry computed inline from finals)
    scan3_kernel<<<(NCH2 * BB * DD) / 256, 256>>>(decay, out);
}